// round 6
// baseline (speedup 1.0000x reference)
#include <cuda_runtime.h>
#include <math.h>

#define N_NODES 100000
#define N_EDGES 1600000
#define HIDDEN  48
#define ALPHA   0.1f
#define NPB     160         // nodes per block (100000 = 625 * 160)
#define LTHREADS 192        // 48 gather groups of 4; GEMM: 16 m-slots x 12 quads
#define SCB     100         // scan blocks
#define SCHUNK  1000        // elements per scan block

// Scratch (__device__ globals: allocation-free rule)
__device__ float g_x0 [N_NODES * HIDDEN];
__device__ float g_h  [N_NODES * HIDDEN];
__device__ float g_hb [N_NODES * HIDDEN];   // ping-pong buffer
__device__ int   g_cnt[N_NODES];
__device__ int   g_row[N_NODES + 1];
__device__ int   g_cur[N_NODES];
__device__ int   g_esrc[N_EDGES];
__device__ int   g_part[SCB];

// ---------------------------------------------------------------------------
// Init: h0 = relu(x @ W0 + b0); x0 = h0. Also zero the degree histogram.
// ---------------------------------------------------------------------------
__global__ void init_kernel(const float* __restrict__ x,
                            const float* __restrict__ W0,
                            const float* __restrict__ b0) {
    int idx = blockIdx.x * blockDim.x + threadIdx.x;
    if (idx < N_NODES) g_cnt[idx] = 0;
    if (idx >= N_NODES * HIDDEN) return;
    int n = idx / HIDDEN;
    int j = idx - n * HIDDEN;
    float v = x[n * 3 + 0] * W0[0 * HIDDEN + j]
            + x[n * 3 + 1] * W0[1 * HIDDEN + j]
            + x[n * 3 + 2] * W0[2 * HIDDEN + j]
            + b0[j];
    v = fmaxf(v, 0.0f);
    g_x0[idx] = v;
    g_h[idx]  = v;
}

// ---------------------------------------------------------------------------
// CSR build: histogram of destination degrees
// ---------------------------------------------------------------------------
__global__ void hist_kernel(const int* __restrict__ ei) {
    int e = blockIdx.x * blockDim.x + threadIdx.x;
    if (e >= N_EDGES) return;
    atomicAdd(&g_cnt[ei[N_EDGES + e]], 1);
}

// ---------------------------------------------------------------------------
// Parallel exclusive scan over g_cnt: A (block sums) -> B (combine) -> C (final)
// ---------------------------------------------------------------------------
__global__ __launch_bounds__(256) void scanA_kernel() {
    __shared__ int s[256];
    int b = blockIdx.x, t = threadIdx.x;
    int sum = 0;
    for (int i = t; i < SCHUNK; i += 256) sum += g_cnt[b * SCHUNK + i];
    s[t] = sum;
    __syncthreads();
    for (int off = 128; off > 0; off >>= 1) {
        if (t < off) s[t] += s[t + off];
        __syncthreads();
    }
    if (t == 0) g_part[b] = s[0];
}

__global__ __launch_bounds__(128) void scanB_kernel() {
    __shared__ int sp[SCB];
    int t = threadIdx.x;
    if (t < SCB) sp[t] = g_part[t];
    __syncthreads();
    if (t == 0) {
        int run = 0;
        for (int i = 0; i < SCB; i++) { int c = sp[i]; sp[i] = run; run += c; }
        g_row[N_NODES] = run;
    }
    __syncthreads();
    if (t < SCB) g_part[t] = sp[t];
}

__global__ __launch_bounds__(1024) void scanC_kernel() {
    __shared__ int s[1024];
    int b = blockIdx.x, t = threadIdx.x;
    int i = b * SCHUNK + t;
    int c = (t < SCHUNK) ? g_cnt[i] : 0;
    s[t] = c;
    __syncthreads();
    for (int off = 1; off < 1024; off <<= 1) {
        int v = (t >= off) ? s[t - off] : 0;
        __syncthreads();
        s[t] += v;
        __syncthreads();
    }
    if (t < SCHUNK) {
        int excl = s[t] - c + g_part[b];
        g_row[i] = excl;
        g_cur[i] = excl;
    }
}

// ---------------------------------------------------------------------------
// CSR build: fill edge source lists
// ---------------------------------------------------------------------------
__global__ void fill_kernel(const int* __restrict__ ei) {
    int e = blockIdx.x * blockDim.x + threadIdx.x;
    if (e >= N_EDGES) return;
    int dst = ei[N_EDGES + e];
    int pos = atomicAdd(&g_cur[dst], 1);
    g_esrc[pos] = ei[e];
}

__device__ __forceinline__ void f4add(float4& a, const float4& b) {
    a.x += b.x; a.y += b.y; a.z += b.z; a.w += b.w;
}

// ---------------------------------------------------------------------------
// Fused layer: balanced gather (4-lane groups, dynamic node claiming)
// + residual mix + register-blocked 48x48 GEMM (2 chunks of 5 nodes) + relu.
// Single-wave: smem ~40.6KB, <=68 regs -> 5 blocks/SM -> 740 slots >= 625.
// flip=0: read g_h, write g_hb.  flip=1: read g_hb, write g_h.
// ---------------------------------------------------------------------------
__global__ __launch_bounds__(LTHREADS, 5)
void layer_fused(const float* __restrict__ convW, float beta, int flip) {
    __shared__ float sW[HIDDEN * HIDDEN];   // 9216 B
    __shared__ float sT[NPB * HIDDEN];      // 30720 B
    __shared__ int   sR[NPB + 1];           // 644 B
    __shared__ int   sClaim;

    const float* __restrict__ hin  = flip ? g_hb : g_h;
    float*       __restrict__ hout = flip ? g_h  : g_hb;

    int tid = threadIdx.x;
    int node0 = blockIdx.x * NPB;

    #pragma unroll
    for (int i = tid; i < HIDDEN * HIDDEN; i += LTHREADS)
        sW[i] = convW[i];
    for (int i = tid; i <= NPB; i += LTHREADS)
        sR[i] = g_row[node0 + i];
    if (tid == 0) sClaim = 0;
    __syncthreads();

    // --- balanced gather: groups of 4 lanes claim nodes dynamically ---
    int lane = tid & 31;
    int c = tid & 3;                          // lane owns floats [12c, 12c+12)
    unsigned submask = 0xFu << (lane & ~3);

    while (true) {
        int n = 0;
        if (c == 0) n = atomicAdd(&sClaim, 1);
        n = __shfl_sync(submask, n, 0, 4);
        if (n >= NPB) break;

        int rs = sR[n], re = sR[n + 1];
        float4 a0 = make_float4(0.f, 0.f, 0.f, 0.f);
        float4 a1 = a0, a2 = a0;

        for (int j = rs; j < re; j++) {
            int s0 = g_esrc[j];
            const float4* p0 = reinterpret_cast<const float4*>(hin + (size_t)s0 * HIDDEN) + 3 * c;
            f4add(a0, p0[0]); f4add(a1, p0[1]); f4add(a2, p0[2]);
        }

        const float4* px = reinterpret_cast<const float4*>(g_x0 + (size_t)(node0 + n) * HIDDEN) + 3 * c;
        float4 x0v0 = px[0], x0v1 = px[1], x0v2 = px[2];
        float4 t0, t1, t2;
        t0.x = (1.0f - ALPHA) * a0.x + ALPHA * x0v0.x;
        t0.y = (1.0f - ALPHA) * a0.y + ALPHA * x0v0.y;
        t0.z = (1.0f - ALPHA) * a0.z + ALPHA * x0v0.z;
        t0.w = (1.0f - ALPHA) * a0.w + ALPHA * x0v0.w;
        t1.x = (1.0f - ALPHA) * a1.x + ALPHA * x0v1.x;
        t1.y = (1.0f - ALPHA) * a1.y + ALPHA * x0v1.y;
        t1.z = (1.0f - ALPHA) * a1.z + ALPHA * x0v1.z;
        t1.w = (1.0f - ALPHA) * a1.w + ALPHA * x0v1.w;
        t2.x = (1.0f - ALPHA) * a2.x + ALPHA * x0v2.x;
        t2.y = (1.0f - ALPHA) * a2.y + ALPHA * x0v2.y;
        t2.z = (1.0f - ALPHA) * a2.z + ALPHA * x0v2.z;
        t2.w = (1.0f - ALPHA) * a2.w + ALPHA * x0v2.w;
        float4* pt = reinterpret_cast<float4*>(sT + n * HIDDEN) + 3 * c;
        pt[0] = t0; pt[1] = t1; pt[2] = t2;
    }
    __syncthreads();

    // --- register-blocked GEMM: 2 chunks x 5 nodes per thread ---
    int q = tid % 12;          // output quad
    int m = tid / 12;          // 0..15
    const float4* sW4 = reinterpret_cast<const float4*>(sW);
    float ob = 1.0f - beta;

    #pragma unroll
    for (int chunk = 0; chunk < 2; chunk++) {
        float4 acc[5];
        #pragma unroll
        for (int i = 0; i < 5; i++) acc[i] = make_float4(0.f, 0.f, 0.f, 0.f);

        for (int k = 0; k < HIDDEN; k++) {
            float4 w = sW4[k * 12 + q];
            #pragma unroll
            for (int i = 0; i < 5; i++) {
                float a = sT[(m + 16 * (chunk * 5 + i)) * HIDDEN + k];
                acc[i].x = fmaf(a, w.x, acc[i].x);
                acc[i].y = fmaf(a, w.y, acc[i].y);
                acc[i].z = fmaf(a, w.z, acc[i].z);
                acc[i].w = fmaf(a, w.w, acc[i].w);
            }
        }
        #pragma unroll
        for (int i = 0; i < 5; i++) {
            int n = m + 16 * (chunk * 5 + i);
            float4 t = *(reinterpret_cast<const float4*>(sT + n * HIDDEN) + q);
            float4 o;
            o.x = fmaxf(ob * t.x + beta * acc[i].x, 0.0f);
            o.y = fmaxf(ob * t.y + beta * acc[i].y, 0.0f);
            o.z = fmaxf(ob * t.z + beta * acc[i].z, 0.0f);
            o.w = fmaxf(ob * t.w + beta * acc[i].w, 0.0f);
            *(reinterpret_cast<float4*>(hout + (size_t)(node0 + n) * HIDDEN) + q) = o;
        }
    }
}

// ---------------------------------------------------------------------------
// Output: z = h @ W1 + b1 ; out = log_softmax(z)   (reads g_h)
// Z is written back into sT (chunked, disjoint row ranges) to stay single-wave.
// ---------------------------------------------------------------------------
__global__ __launch_bounds__(LTHREADS, 5)
void out_kernel(const float* __restrict__ W1,
                const float* __restrict__ b1,
                float* __restrict__ out) {
    __shared__ float sW[HIDDEN * HIDDEN];   // 9216 B
    __shared__ float sT[NPB * HIDDEN];      // 30720 B (h, then Z in-place)
    __shared__ float sLS[NPB];              // 640 B

    int tid = threadIdx.x;
    int node0 = blockIdx.x * NPB;
    int base = node0 * HIDDEN;

    #pragma unroll
    for (int i = tid; i < HIDDEN * HIDDEN; i += LTHREADS)
        sW[i] = W1[i];
    {
        const float4* gh4 = reinterpret_cast<const float4*>(g_h + base);
        float4* sT4 = reinterpret_cast<float4*>(sT);
        for (int i = tid; i < NPB * HIDDEN / 4; i += LTHREADS)
            sT4[i] = gh4[i];
    }
    __syncthreads();

    int q = tid % 12;
    int m = tid / 12;
    const float4* sW4 = reinterpret_cast<const float4*>(sW);
    float4 bv = reinterpret_cast<const float4*>(b1)[q];

    // chunk 0: GEMM over nodes 0..79, then write Z in place (sync first)
    // chunk 1: GEMM over nodes 80..159 (rows untouched by chunk-0 writes)
    #pragma unroll
    for (int chunk = 0; chunk < 2; chunk++) {
        float4 acc[5];
        #pragma unroll
        for (int i = 0; i < 5; i++) acc[i] = bv;

        for (int k = 0; k < HIDDEN; k++) {
            float4 w = sW4[k * 12 + q];
            #pragma unroll
            for (int i = 0; i < 5; i++) {
                float a = sT[(m + 16 * (chunk * 5 + i)) * HIDDEN + k];
                acc[i].x = fmaf(a, w.x, acc[i].x);
                acc[i].y = fmaf(a, w.y, acc[i].y);
                acc[i].z = fmaf(a, w.z, acc[i].z);
                acc[i].w = fmaf(a, w.w, acc[i].w);
            }
        }
        __syncthreads();   // all reads of this chunk's source rows done
        #pragma unroll
        for (int i = 0; i < 5; i++) {
            int n = m + 16 * (chunk * 5 + i);
            *(reinterpret_cast<float4*>(sT + n * HIDDEN) + q) = acc[i];
        }
    }
    __syncthreads();

    if (tid < NPB) {
        float mx = -INFINITY;
        #pragma unroll
        for (int k = 0; k < HIDDEN; k++)
            mx = fmaxf(mx, sT[tid * HIDDEN + k]);
        float s = 0.0f;
        #pragma unroll
        for (int k = 0; k < HIDDEN; k++)
            s += expf(sT[tid * HIDDEN + k] - mx);
        sLS[tid] = mx + logf(s);
    }
    __syncthreads();

    #pragma unroll
    for (int i = 0; i < 10; i++) {
        int n = m + 16 * i;
        float ls = sLS[n];
        float4 z = *(reinterpret_cast<const float4*>(sT + n * HIDDEN) + q);
        float4 o;
        o.x = z.x - ls; o.y = z.y - ls; o.z = z.z - ls; o.w = z.w - ls;
        *(reinterpret_cast<float4*>(out + (size_t)base + n * HIDDEN) + q) = o;
    }
}

// ---------------------------------------------------------------------------
extern "C" void kernel_launch(void* const* d_in, const int* in_sizes, int n_in,
                              void* d_out, int out_size) {
    const float* x     = (const float*)d_in[0];
    const int*   ei    = (const int*)  d_in[1];
    const float* W0    = (const float*)d_in[2];
    const float* b0    = (const float*)d_in[3];
    const float* convW = (const float*)d_in[4];
    const float* W1    = (const float*)d_in[5];
    const float* b1    = (const float*)d_in[6];
    float* out = (float*)d_out;

    // beta_l = log(0.5/(l+1) + 1)
    const float betas[4] = {0.4054651081f, 0.2231435513f,
                            0.1541506798f, 0.1177830357f};

    const int it = 256;
    init_kernel<<<(N_NODES * HIDDEN + it - 1) / it, it>>>(x, W0, b0);

    const int et = 256;
    const int eb = (N_EDGES + et - 1) / et;
    hist_kernel<<<eb, et>>>(ei);
    scanA_kernel<<<SCB, 256>>>();
    scanB_kernel<<<1, 128>>>();
    scanC_kernel<<<SCB, 1024>>>();
    fill_kernel<<<eb, et>>>(ei);

    const int node_blocks = N_NODES / NPB;   // 625
    for (int l = 0; l < 4; l++)
        layer_fused<<<node_blocks, LTHREADS>>>(convW + l * HIDDEN * HIDDEN,
                                               betas[l], l & 1);

    // layers 0..3: h path g_h -> g_hb -> g_h -> g_hb -> g_h (final in g_h)
    out_kernel<<<node_blocks, LTHREADS>>>(W1, b1, out);
}

// round 7
// speedup vs baseline: 1.0350x; 1.0350x over previous
#include <cuda_runtime.h>
#include <math.h>

#define N_NODES 100000
#define N_EDGES 1600000
#define HIDDEN  48
#define ALPHA   0.1f
#define NPB     160         // nodes per block (100000 = 625 * 160)
#define LTHREADS 192        // 48 gather groups of 4; GEMM: 16 m-slots x 12 quads
#define ECAP    3584        // smem edge-index buffer (mean 2560, +6 sigma)
#define SCB     100         // scan blocks
#define SCHUNK  1000        // elements per scan block

// Scratch (__device__ globals: allocation-free rule)
__device__ float g_x0 [N_NODES * HIDDEN];
__device__ float g_h  [N_NODES * HIDDEN];
__device__ float g_hb [N_NODES * HIDDEN];   // ping-pong buffer
__device__ float g_t  [N_NODES * HIDDEN];   // mixed pre-GEMM features
__device__ int   g_cnt[N_NODES];
__device__ int   g_row[N_NODES + 1];
__device__ int   g_cur[N_NODES];
__device__ int   g_esrc[N_EDGES];
__device__ int   g_part[SCB];

// ---------------------------------------------------------------------------
// Init: h0 = relu(x @ W0 + b0); x0 = h0. Also zero the degree histogram.
// ---------------------------------------------------------------------------
__global__ void init_kernel(const float* __restrict__ x,
                            const float* __restrict__ W0,
                            const float* __restrict__ b0) {
    int idx = blockIdx.x * blockDim.x + threadIdx.x;
    if (idx < N_NODES) g_cnt[idx] = 0;
    if (idx >= N_NODES * HIDDEN) return;
    int n = idx / HIDDEN;
    int j = idx - n * HIDDEN;
    float v = x[n * 3 + 0] * W0[0 * HIDDEN + j]
            + x[n * 3 + 1] * W0[1 * HIDDEN + j]
            + x[n * 3 + 2] * W0[2 * HIDDEN + j]
            + b0[j];
    v = fmaxf(v, 0.0f);
    g_x0[idx] = v;
    g_h[idx]  = v;
}

// ---------------------------------------------------------------------------
// CSR build: histogram of destination degrees
// ---------------------------------------------------------------------------
__global__ void hist_kernel(const int* __restrict__ ei) {
    int e = blockIdx.x * blockDim.x + threadIdx.x;
    if (e >= N_EDGES) return;
    atomicAdd(&g_cnt[ei[N_EDGES + e]], 1);
}

// ---------------------------------------------------------------------------
// Scan A: per-block sums of g_cnt
// ---------------------------------------------------------------------------
__global__ __launch_bounds__(256) void scanA_kernel() {
    __shared__ int s[256];
    int b = blockIdx.x, t = threadIdx.x;
    int sum = 0;
    for (int i = t; i < SCHUNK; i += 256) sum += g_cnt[b * SCHUNK + i];
    s[t] = sum;
    __syncthreads();
    for (int off = 128; off > 0; off >>= 1) {
        if (t < off) s[t] += s[t + off];
        __syncthreads();
    }
    if (t == 0) g_part[b] = s[0];
}

// ---------------------------------------------------------------------------
// Scan C: final exclusive scan; block offset computed in-block from g_part
// (folds the old scanB kernel away).
// ---------------------------------------------------------------------------
__global__ __launch_bounds__(1024) void scanC_kernel() {
    __shared__ int s[1024];
    __shared__ int sOff;
    int b = blockIdx.x, t = threadIdx.x;
    if (t == 0) sOff = 0;
    __syncthreads();
    if (t < b) atomicAdd(&sOff, g_part[t]);   // b <= 99

    int i = b * SCHUNK + t;
    int c = (t < SCHUNK) ? g_cnt[i] : 0;
    s[t] = c;
    __syncthreads();
    for (int off = 1; off < 1024; off <<= 1) {
        int v = (t >= off) ? s[t - off] : 0;
        __syncthreads();
        s[t] += v;
        __syncthreads();
    }
    int off = sOff;
    if (t < SCHUNK) {
        int excl = s[t] - c + off;
        g_row[i] = excl;
        g_cur[i] = excl;
    }
    if (b == SCB - 1 && t == SCHUNK - 1)
        g_row[N_NODES] = s[t] + off;
}

// ---------------------------------------------------------------------------
// CSR build: fill edge source lists
// ---------------------------------------------------------------------------
__global__ void fill_kernel(const int* __restrict__ ei) {
    int e = blockIdx.x * blockDim.x + threadIdx.x;
    if (e >= N_EDGES) return;
    int dst = ei[N_EDGES + e];
    int pos = atomicAdd(&g_cur[dst], 1);
    g_esrc[pos] = ei[e];
}

__device__ __forceinline__ void f4add(float4& a, const float4& b) {
    a.x += b.x; a.y += b.y; a.z += b.z; a.w += b.w;
}
__device__ __forceinline__ void f4add2(float4& a, const float4& b, const float4& c) {
    a.x += b.x + c.x; a.y += b.y + c.y; a.z += b.z + c.z; a.w += b.w + c.w;
}

// ---------------------------------------------------------------------------
// Gather: balanced pull (4-lane groups, dynamic claiming, smem-staged indices,
// 2-edge unroll). Writes t = 0.9*agg + 0.1*x0 to g_t. Low smem -> ~10 blk/SM.
// flip=0: read g_h.  flip=1: read g_hb.
// ---------------------------------------------------------------------------
__global__ __launch_bounds__(LTHREADS)
void gather_kernel(int flip) {
    __shared__ int sE[ECAP];                // 14336 B
    __shared__ int sR[NPB + 1];             // 644 B
    __shared__ int sClaim;

    const float* __restrict__ hin = flip ? g_hb : g_h;

    int tid = threadIdx.x;
    int node0 = blockIdx.x * NPB;

    for (int i = tid; i <= NPB; i += LTHREADS)
        sR[i] = g_row[node0 + i];
    if (tid == 0) sClaim = 0;
    __syncthreads();

    int eStart = sR[0];
    int eCount = sR[NPB] - eStart;
    bool inSmem = (eCount <= ECAP);
    if (inSmem) {
        for (int i = tid; i < eCount; i += LTHREADS)
            sE[i] = g_esrc[eStart + i];
    }
    __syncthreads();

    int lane = tid & 31;
    int c = tid & 3;                          // lane owns floats [12c, 12c+12)
    unsigned submask = 0xFu << (lane & ~3);

    while (true) {
        int n = 0;
        if (c == 0) n = atomicAdd(&sClaim, 1);
        n = __shfl_sync(submask, n, 0, 4);
        if (n >= NPB) break;

        int rs = sR[n], re = sR[n + 1];
        float4 a0 = make_float4(0.f, 0.f, 0.f, 0.f);
        float4 a1 = a0, a2 = a0;

        if (inSmem) {
            int j = rs - eStart, je = re - eStart;
            for (; j + 2 <= je; j += 2) {
                int s0 = sE[j], s1 = sE[j + 1];
                const float4* p0 = reinterpret_cast<const float4*>(hin + (size_t)s0 * HIDDEN) + 3 * c;
                const float4* p1 = reinterpret_cast<const float4*>(hin + (size_t)s1 * HIDDEN) + 3 * c;
                float4 u0 = p0[0], u1 = p0[1], u2 = p0[2];
                float4 w0 = p1[0], w1 = p1[1], w2 = p1[2];
                f4add2(a0, u0, w0); f4add2(a1, u1, w1); f4add2(a2, u2, w2);
            }
            if (j < je) {
                int s0 = sE[j];
                const float4* p0 = reinterpret_cast<const float4*>(hin + (size_t)s0 * HIDDEN) + 3 * c;
                f4add(a0, p0[0]); f4add(a1, p0[1]); f4add(a2, p0[2]);
            }
        } else {
            int j = rs, je = re;
            for (; j + 2 <= je; j += 2) {
                int s0 = g_esrc[j], s1 = g_esrc[j + 1];
                const float4* p0 = reinterpret_cast<const float4*>(hin + (size_t)s0 * HIDDEN) + 3 * c;
                const float4* p1 = reinterpret_cast<const float4*>(hin + (size_t)s1 * HIDDEN) + 3 * c;
                float4 u0 = p0[0], u1 = p0[1], u2 = p0[2];
                float4 w0 = p1[0], w1 = p1[1], w2 = p1[2];
                f4add2(a0, u0, w0); f4add2(a1, u1, w1); f4add2(a2, u2, w2);
            }
            if (j < je) {
                int s0 = g_esrc[j];
                const float4* p0 = reinterpret_cast<const float4*>(hin + (size_t)s0 * HIDDEN) + 3 * c;
                f4add(a0, p0[0]); f4add(a1, p0[1]); f4add(a2, p0[2]);
            }
        }

        size_t nbase = (size_t)(node0 + n) * HIDDEN;
        const float4* px = reinterpret_cast<const float4*>(g_x0 + nbase) + 3 * c;
        float4 x0v0 = px[0], x0v1 = px[1], x0v2 = px[2];
        float4 t0, t1, t2;
        t0.x = (1.0f - ALPHA) * a0.x + ALPHA * x0v0.x;
        t0.y = (1.0f - ALPHA) * a0.y + ALPHA * x0v0.y;
        t0.z = (1.0f - ALPHA) * a0.z + ALPHA * x0v0.z;
        t0.w = (1.0f - ALPHA) * a0.w + ALPHA * x0v0.w;
        t1.x = (1.0f - ALPHA) * a1.x + ALPHA * x0v1.x;
        t1.y = (1.0f - ALPHA) * a1.y + ALPHA * x0v1.y;
        t1.z = (1.0f - ALPHA) * a1.z + ALPHA * x0v1.z;
        t1.w = (1.0f - ALPHA) * a1.w + ALPHA * x0v1.w;
        t2.x = (1.0f - ALPHA) * a2.x + ALPHA * x0v2.x;
        t2.y = (1.0f - ALPHA) * a2.y + ALPHA * x0v2.y;
        t2.z = (1.0f - ALPHA) * a2.z + ALPHA * x0v2.z;
        t2.w = (1.0f - ALPHA) * a2.w + ALPHA * x0v2.w;
        float4* pt = reinterpret_cast<float4*>(g_t + nbase) + 3 * c;
        pt[0] = t0; pt[1] = t1; pt[2] = t2;
    }
}

// ---------------------------------------------------------------------------
// GEMM: h_out = relu((1-beta)*t + beta * t@W). Reads g_t coalesced into sT.
// smem ~40KB -> 5 blocks/SM -> 740 slots >= 625 -> single wave.
// flip=0: write g_hb.  flip=1: write g_h.
// ---------------------------------------------------------------------------
__global__ __launch_bounds__(LTHREADS, 5)
void gemm_kernel(const float* __restrict__ convW, float beta, int flip) {
    __shared__ float sW[HIDDEN * HIDDEN];   // 9216 B
    __shared__ float sT[NPB * HIDDEN];      // 30720 B

    float* __restrict__ hout = flip ? g_h : g_hb;

    int tid = threadIdx.x;
    int node0 = blockIdx.x * NPB;
    int base = node0 * HIDDEN;

    #pragma unroll
    for (int i = tid; i < HIDDEN * HIDDEN; i += LTHREADS)
        sW[i] = convW[i];
    {
        const float4* gt4 = reinterpret_cast<const float4*>(g_t + base);
        float4* sT4 = reinterpret_cast<float4*>(sT);
        for (int i = tid; i < NPB * HIDDEN / 4; i += LTHREADS)
            sT4[i] = gt4[i];
    }
    __syncthreads();

    int q = tid % 12;          // output quad
    int m = tid / 12;          // 0..15
    const float4* sW4 = reinterpret_cast<const float4*>(sW);
    float ob = 1.0f - beta;

    #pragma unroll
    for (int chunk = 0; chunk < 2; chunk++) {
        float4 acc[5];
        #pragma unroll
        for (int i = 0; i < 5; i++) acc[i] = make_float4(0.f, 0.f, 0.f, 0.f);

        for (int k = 0; k < HIDDEN; k++) {
            float4 w = sW4[k * 12 + q];
            #pragma unroll
            for (int i = 0; i < 5; i++) {
                float a = sT[(m + 16 * (chunk * 5 + i)) * HIDDEN + k];
                acc[i].x = fmaf(a, w.x, acc[i].x);
                acc[i].y = fmaf(a, w.y, acc[i].y);
                acc[i].z = fmaf(a, w.z, acc[i].z);
                acc[i].w = fmaf(a, w.w, acc[i].w);
            }
        }
        #pragma unroll
        for (int i = 0; i < 5; i++) {
            int n = m + 16 * (chunk * 5 + i);
            float4 t = *(reinterpret_cast<const float4*>(sT + n * HIDDEN) + q);
            float4 o;
            o.x = fmaxf(ob * t.x + beta * acc[i].x, 0.0f);
            o.y = fmaxf(ob * t.y + beta * acc[i].y, 0.0f);
            o.z = fmaxf(ob * t.z + beta * acc[i].z, 0.0f);
            o.w = fmaxf(ob * t.w + beta * acc[i].w, 0.0f);
            *(reinterpret_cast<float4*>(hout + (size_t)(node0 + n) * HIDDEN) + q) = o;
        }
    }
}

// ---------------------------------------------------------------------------
// Output: z = h @ W1 + b1 ; out = log_softmax(z)   (reads g_h)
// Z written back into sT (chunked, disjoint rows). Single wave.
// ---------------------------------------------------------------------------
__global__ __launch_bounds__(LTHREADS, 5)
void out_kernel(const float* __restrict__ W1,
                const float* __restrict__ b1,
                float* __restrict__ out) {
    __shared__ float sW[HIDDEN * HIDDEN];   // 9216 B
    __shared__ float sT[NPB * HIDDEN];      // 30720 B (h, then Z in-place)
    __shared__ float sLS[NPB];              // 640 B

    int tid = threadIdx.x;
    int node0 = blockIdx.x * NPB;
    int base = node0 * HIDDEN;

    #pragma unroll
    for (int i = tid; i < HIDDEN * HIDDEN; i += LTHREADS)
        sW[i] = W1[i];
    {
        const float4* gh4 = reinterpret_cast<const float4*>(g_h + base);
        float4* sT4 = reinterpret_cast<float4*>(sT);
        for (int i = tid; i < NPB * HIDDEN / 4; i += LTHREADS)
            sT4[i] = gh4[i];
    }
    __syncthreads();

    int q = tid % 12;
    int m = tid / 12;
    const float4* sW4 = reinterpret_cast<const float4*>(sW);
    float4 bv = reinterpret_cast<const float4*>(b1)[q];

    #pragma unroll
    for (int chunk = 0; chunk < 2; chunk++) {
        float4 acc[5];
        #pragma unroll
        for (int i = 0; i < 5; i++) acc[i] = bv;

        for (int k = 0; k < HIDDEN; k++) {
            float4 w = sW4[k * 12 + q];
            #pragma unroll
            for (int i = 0; i < 5; i++) {
                float a = sT[(m + 16 * (chunk * 5 + i)) * HIDDEN + k];
                acc[i].x = fmaf(a, w.x, acc[i].x);
                acc[i].y = fmaf(a, w.y, acc[i].y);
                acc[i].z = fmaf(a, w.z, acc[i].z);
                acc[i].w = fmaf(a, w.w, acc[i].w);
            }
        }
        __syncthreads();   // all reads of this chunk's source rows done
        #pragma unroll
        for (int i = 0; i < 5; i++) {
            int n = m + 16 * (chunk * 5 + i);
            *(reinterpret_cast<float4*>(sT + n * HIDDEN) + q) = acc[i];
        }
    }
    __syncthreads();

    if (tid < NPB) {
        float mx = -INFINITY;
        #pragma unroll
        for (int k = 0; k < HIDDEN; k++)
            mx = fmaxf(mx, sT[tid * HIDDEN + k]);
        float s = 0.0f;
        #pragma unroll
        for (int k = 0; k < HIDDEN; k++)
            s += expf(sT[tid * HIDDEN + k] - mx);
        sLS[tid] = mx + logf(s);
    }
    __syncthreads();

    #pragma unroll
    for (int i = 0; i < 10; i++) {
        int n = m + 16 * i;
        float ls = sLS[n];
        float4 z = *(reinterpret_cast<const float4*>(sT + n * HIDDEN) + q);
        float4 o;
        o.x = z.x - ls; o.y = z.y - ls; o.z = z.z - ls; o.w = z.w - ls;
        *(reinterpret_cast<float4*>(out + (size_t)base + n * HIDDEN) + q) = o;
    }
}

// ---------------------------------------------------------------------------
extern "C" void kernel_launch(void* const* d_in, const int* in_sizes, int n_in,
                              void* d_out, int out_size) {
    const float* x     = (const float*)d_in[0];
    const int*   ei    = (const int*)  d_in[1];
    const float* W0    = (const float*)d_in[2];
    const float* b0    = (const float*)d_in[3];
    const float* convW = (const float*)d_in[4];
    const float* W1    = (const float*)d_in[5];
    const float* b1    = (const float*)d_in[6];
    float* out = (float*)d_out;

    // beta_l = log(0.5/(l+1) + 1)
    const float betas[4] = {0.4054651081f, 0.2231435513f,
                            0.1541506798f, 0.1177830357f};

    const int it = 256;
    init_kernel<<<(N_NODES * HIDDEN + it - 1) / it, it>>>(x, W0, b0);

    const int et = 256;
    const int eb = (N_EDGES + et - 1) / et;
    hist_kernel<<<eb, et>>>(ei);
    scanA_kernel<<<SCB, 256>>>();
    scanC_kernel<<<SCB, 1024>>>();
    fill_kernel<<<eb, et>>>(ei);

    const int node_blocks = N_NODES / NPB;   // 625
    for (int l = 0; l < 4; l++) {
        gather_kernel<<<node_blocks, LTHREADS>>>(l & 1);
        gemm_kernel<<<node_blocks, LTHREADS>>>(convW + l * HIDDEN * HIDDEN,
                                               betas[l], l & 1);
    }

    // layers 0..3: h path g_h -> g_hb -> g_h -> g_hb -> g_h (final in g_h)
    out_kernel<<<node_blocks, LTHREADS>>>(W1, b1, out);
}

// round 8
// speedup vs baseline: 1.1662x; 1.1268x over previous
#include <cuda_runtime.h>
#include <math.h>

#define N_NODES 100000
#define N_EDGES 1600000
#define HIDDEN  48
#define ALPHA   0.1f
#define NPB     160         // nodes per block (100000 = 625 * 160)
#define LTHREADS 192        // 48 gather groups of 4; GEMM: 16 m-slots x 12 quads
#define ECAP    3584        // smem edge-index buffer (mean 2560, +6 sigma)
#define SCB     100         // scan blocks
#define SCHUNK  1000        // elements per scan block

// Scratch (__device__ globals: allocation-free rule)
__device__ float g_x0 [N_NODES * HIDDEN];
__device__ float g_h  [N_NODES * HIDDEN];
__device__ float g_hb [N_NODES * HIDDEN];   // ping-pong buffer
__device__ float g_t  [N_NODES * HIDDEN];   // mixed pre-GEMM features
__device__ int   g_cnt[N_NODES];
__device__ int   g_row[N_NODES + 1];
__device__ int   g_cur[N_NODES];
__device__ int   g_esrc[N_EDGES];
__device__ int   g_part[SCB];

// ---------------------------------------------------------------------------
// Init: h0 = relu(x @ W0 + b0); x0 = h0. Also zero the degree histogram.
// ---------------------------------------------------------------------------
__global__ void init_kernel(const float* __restrict__ x,
                            const float* __restrict__ W0,
                            const float* __restrict__ b0) {
    int idx = blockIdx.x * blockDim.x + threadIdx.x;
    if (idx < N_NODES) g_cnt[idx] = 0;
    if (idx >= N_NODES * HIDDEN) return;
    int n = idx / HIDDEN;
    int j = idx - n * HIDDEN;
    float v = x[n * 3 + 0] * W0[0 * HIDDEN + j]
            + x[n * 3 + 1] * W0[1 * HIDDEN + j]
            + x[n * 3 + 2] * W0[2 * HIDDEN + j]
            + b0[j];
    v = fmaxf(v, 0.0f);
    g_x0[idx] = v;
    g_h[idx]  = v;
}

// ---------------------------------------------------------------------------
// CSR build: histogram of destination degrees
// ---------------------------------------------------------------------------
__global__ void hist_kernel(const int* __restrict__ ei) {
    int e = blockIdx.x * blockDim.x + threadIdx.x;
    if (e >= N_EDGES) return;
    atomicAdd(&g_cnt[ei[N_EDGES + e]], 1);
}

// ---------------------------------------------------------------------------
// Scan A: per-block sums of g_cnt
// ---------------------------------------------------------------------------
__global__ __launch_bounds__(256) void scanA_kernel() {
    __shared__ int s[256];
    int b = blockIdx.x, t = threadIdx.x;
    int sum = 0;
    for (int i = t; i < SCHUNK; i += 256) sum += g_cnt[b * SCHUNK + i];
    s[t] = sum;
    __syncthreads();
    for (int off = 128; off > 0; off >>= 1) {
        if (t < off) s[t] += s[t + off];
        __syncthreads();
    }
    if (t == 0) g_part[b] = s[0];
}

// ---------------------------------------------------------------------------
// Scan C: final exclusive scan; block offset computed in-block from g_part.
// ---------------------------------------------------------------------------
__global__ __launch_bounds__(1024) void scanC_kernel() {
    __shared__ int s[1024];
    __shared__ int sOff;
    int b = blockIdx.x, t = threadIdx.x;
    if (t == 0) sOff = 0;
    __syncthreads();
    if (t < b) atomicAdd(&sOff, g_part[t]);   // b <= 99

    int i = b * SCHUNK + t;
    int c = (t < SCHUNK) ? g_cnt[i] : 0;
    s[t] = c;
    __syncthreads();
    for (int off = 1; off < 1024; off <<= 1) {
        int v = (t >= off) ? s[t - off] : 0;
        __syncthreads();
        s[t] += v;
        __syncthreads();
    }
    int off = sOff;
    if (t < SCHUNK) {
        int excl = s[t] - c + off;
        g_row[i] = excl;
        g_cur[i] = excl;
    }
    if (b == SCB - 1 && t == SCHUNK - 1)
        g_row[N_NODES] = s[t] + off;
}

// ---------------------------------------------------------------------------
// CSR build: fill edge source lists
// ---------------------------------------------------------------------------
__global__ void fill_kernel(const int* __restrict__ ei) {
    int e = blockIdx.x * blockDim.x + threadIdx.x;
    if (e >= N_EDGES) return;
    int dst = ei[N_EDGES + e];
    int pos = atomicAdd(&g_cur[dst], 1);
    g_esrc[pos] = ei[e];
}

__device__ __forceinline__ void f4add(float4& a, const float4& b) {
    a.x += b.x; a.y += b.y; a.z += b.z; a.w += b.w;
}
__device__ __forceinline__ void f4add2(float4& a, const float4& b, const float4& c) {
    a.x += b.x + c.x; a.y += b.y + c.y; a.z += b.z + c.z; a.w += b.w + c.w;
}

// ---------------------------------------------------------------------------
// Gather: balanced pull (4-lane groups, dynamic claiming, smem-staged indices,
// 2-edge unroll). INTERLEAVED lane ownership: lane c owns float4 idx {c, c+4,
// c+8}, so each LDG.128 covers a contiguous 64B per group (wavefront-friendly).
// Writes t = 0.9*agg + 0.1*x0 to g_t.
// flip=0: read g_h.  flip=1: read g_hb.
// ---------------------------------------------------------------------------
__global__ __launch_bounds__(LTHREADS)
void gather_kernel(int flip) {
    __shared__ int sE[ECAP];                // 14336 B
    __shared__ int sR[NPB + 1];             // 644 B
    __shared__ int sClaim;

    const float* __restrict__ hin = flip ? g_hb : g_h;

    int tid = threadIdx.x;
    int node0 = blockIdx.x * NPB;

    for (int i = tid; i <= NPB; i += LTHREADS)
        sR[i] = g_row[node0 + i];
    if (tid == 0) sClaim = 0;
    __syncthreads();

    int eStart = sR[0];
    int eCount = sR[NPB] - eStart;
    bool inSmem = (eCount <= ECAP);
    if (inSmem) {
        for (int i = tid; i < eCount; i += LTHREADS)
            sE[i] = g_esrc[eStart + i];
    }
    __syncthreads();

    int lane = tid & 31;
    int c = tid & 3;                          // interleave: float4 idx c, c+4, c+8
    unsigned submask = 0xFu << (lane & ~3);

    while (true) {
        int n = 0;
        if (c == 0) n = atomicAdd(&sClaim, 1);
        n = __shfl_sync(submask, n, 0, 4);
        if (n >= NPB) break;

        int rs = sR[n], re = sR[n + 1];
        float4 a0 = make_float4(0.f, 0.f, 0.f, 0.f);
        float4 a1 = a0, a2 = a0;

        if (inSmem) {
            int j = rs - eStart, je = re - eStart;
            for (; j + 2 <= je; j += 2) {
                int s0 = sE[j], s1 = sE[j + 1];
                const float4* p0 = reinterpret_cast<const float4*>(hin + (size_t)s0 * HIDDEN) + c;
                const float4* p1 = reinterpret_cast<const float4*>(hin + (size_t)s1 * HIDDEN) + c;
                float4 u0 = p0[0], u1 = p0[4], u2 = p0[8];
                float4 w0 = p1[0], w1 = p1[4], w2 = p1[8];
                f4add2(a0, u0, w0); f4add2(a1, u1, w1); f4add2(a2, u2, w2);
            }
            if (j < je) {
                int s0 = sE[j];
                const float4* p0 = reinterpret_cast<const float4*>(hin + (size_t)s0 * HIDDEN) + c;
                f4add(a0, p0[0]); f4add(a1, p0[4]); f4add(a2, p0[8]);
            }
        } else {
            int j = rs, je = re;
            for (; j + 2 <= je; j += 2) {
                int s0 = g_esrc[j], s1 = g_esrc[j + 1];
                const float4* p0 = reinterpret_cast<const float4*>(hin + (size_t)s0 * HIDDEN) + c;
                const float4* p1 = reinterpret_cast<const float4*>(hin + (size_t)s1 * HIDDEN) + c;
                float4 u0 = p0[0], u1 = p0[4], u2 = p0[8];
                float4 w0 = p1[0], w1 = p1[4], w2 = p1[8];
                f4add2(a0, u0, w0); f4add2(a1, u1, w1); f4add2(a2, u2, w2);
            }
            if (j < je) {
                int s0 = g_esrc[j];
                const float4* p0 = reinterpret_cast<const float4*>(hin + (size_t)s0 * HIDDEN) + c;
                f4add(a0, p0[0]); f4add(a1, p0[4]); f4add(a2, p0[8]);
            }
        }

        size_t nbase = (size_t)(node0 + n) * HIDDEN;
        const float4* px = reinterpret_cast<const float4*>(g_x0 + nbase) + c;
        float4 x0v0 = px[0], x0v1 = px[4], x0v2 = px[8];
        float4 t0, t1, t2;
        t0.x = (1.0f - ALPHA) * a0.x + ALPHA * x0v0.x;
        t0.y = (1.0f - ALPHA) * a0.y + ALPHA * x0v0.y;
        t0.z = (1.0f - ALPHA) * a0.z + ALPHA * x0v0.z;
        t0.w = (1.0f - ALPHA) * a0.w + ALPHA * x0v0.w;
        t1.x = (1.0f - ALPHA) * a1.x + ALPHA * x0v1.x;
        t1.y = (1.0f - ALPHA) * a1.y + ALPHA * x0v1.y;
        t1.z = (1.0f - ALPHA) * a1.z + ALPHA * x0v1.z;
        t1.w = (1.0f - ALPHA) * a1.w + ALPHA * x0v1.w;
        t2.x = (1.0f - ALPHA) * a2.x + ALPHA * x0v2.x;
        t2.y = (1.0f - ALPHA) * a2.y + ALPHA * x0v2.y;
        t2.z = (1.0f - ALPHA) * a2.z + ALPHA * x0v2.z;
        t2.w = (1.0f - ALPHA) * a2.w + ALPHA * x0v2.w;
        float4* pt = reinterpret_cast<float4*>(g_t + nbase) + c;
        pt[0] = t0; pt[4] = t1; pt[8] = t2;
    }
}

// ---------------------------------------------------------------------------
// GEMM: h_out = relu((1-beta)*t + beta * t@W). Reads g_t coalesced into sT.
// smem ~40KB -> 5 blocks/SM -> 740 slots >= 625 -> single wave.
// flip=0: write g_hb.  flip=1: write g_h.
// ---------------------------------------------------------------------------
__global__ __launch_bounds__(LTHREADS, 5)
void gemm_kernel(const float* __restrict__ convW, float beta, int flip) {
    __shared__ float sW[HIDDEN * HIDDEN];   // 9216 B
    __shared__ float sT[NPB * HIDDEN];      // 30720 B

    float* __restrict__ hout = flip ? g_h : g_hb;

    int tid = threadIdx.x;
    int node0 = blockIdx.x * NPB;
    int base = node0 * HIDDEN;

    #pragma unroll
    for (int i = tid; i < HIDDEN * HIDDEN; i += LTHREADS)
        sW[i] = convW[i];
    {
        const float4* gt4 = reinterpret_cast<const float4*>(g_t + base);
        float4* sT4 = reinterpret_cast<float4*>(sT);
        for (int i = tid; i < NPB * HIDDEN / 4; i += LTHREADS)
            sT4[i] = gt4[i];
    }
    __syncthreads();

    int q = tid % 12;          // output quad
    int m = tid / 12;          // 0..15
    const float4* sW4 = reinterpret_cast<const float4*>(sW);
    float ob = 1.0f - beta;

    #pragma unroll
    for (int chunk = 0; chunk < 2; chunk++) {
        float4 acc[5];
        #pragma unroll
        for (int i = 0; i < 5; i++) acc[i] = make_float4(0.f, 0.f, 0.f, 0.f);

        for (int k = 0; k < HIDDEN; k++) {
            float4 w = sW4[k * 12 + q];
            #pragma unroll
            for (int i = 0; i < 5; i++) {
                float a = sT[(m + 16 * (chunk * 5 + i)) * HIDDEN + k];
                acc[i].x = fmaf(a, w.x, acc[i].x);
                acc[i].y = fmaf(a, w.y, acc[i].y);
                acc[i].z = fmaf(a, w.z, acc[i].z);
                acc[i].w = fmaf(a, w.w, acc[i].w);
            }
        }
        #pragma unroll
        for (int i = 0; i < 5; i++) {
            int n = m + 16 * (chunk * 5 + i);
            float4 t = *(reinterpret_cast<const float4*>(sT + n * HIDDEN) + q);
            float4 o;
            o.x = fmaxf(ob * t.x + beta * acc[i].x, 0.0f);
            o.y = fmaxf(ob * t.y + beta * acc[i].y, 0.0f);
            o.z = fmaxf(ob * t.z + beta * acc[i].z, 0.0f);
            o.w = fmaxf(ob * t.w + beta * acc[i].w, 0.0f);
            *(reinterpret_cast<float4*>(hout + (size_t)(node0 + n) * HIDDEN) + q) = o;
        }
    }
}

// ---------------------------------------------------------------------------
// Output: z = h @ W1 + b1 ; out = log_softmax(z)   (reads g_h)
// Z written back into sT (chunked, disjoint rows). Single wave.
// ---------------------------------------------------------------------------
__global__ __launch_bounds__(LTHREADS, 5)
void out_kernel(const float* __restrict__ W1,
                const float* __restrict__ b1,
                float* __restrict__ out) {
    __shared__ float sW[HIDDEN * HIDDEN];   // 9216 B
    __shared__ float sT[NPB * HIDDEN];      // 30720 B (h, then Z in-place)
    __shared__ float sLS[NPB];              // 640 B

    int tid = threadIdx.x;
    int node0 = blockIdx.x * NPB;
    int base = node0 * HIDDEN;

    #pragma unroll
    for (int i = tid; i < HIDDEN * HIDDEN; i += LTHREADS)
        sW[i] = W1[i];
    {
        const float4* gh4 = reinterpret_cast<const float4*>(g_h + base);
        float4* sT4 = reinterpret_cast<float4*>(sT);
        for (int i = tid; i < NPB * HIDDEN / 4; i += LTHREADS)
            sT4[i] = gh4[i];
    }
    __syncthreads();

    int q = tid % 12;
    int m = tid / 12;
    const float4* sW4 = reinterpret_cast<const float4*>(sW);
    float4 bv = reinterpret_cast<const float4*>(b1)[q];

    #pragma unroll
    for (int chunk = 0; chunk < 2; chunk++) {
        float4 acc[5];
        #pragma unroll
        for (int i = 0; i < 5; i++) acc[i] = bv;

        for (int k = 0; k < HIDDEN; k++) {
            float4 w = sW4[k * 12 + q];
            #pragma unroll
            for (int i = 0; i < 5; i++) {
                float a = sT[(m + 16 * (chunk * 5 + i)) * HIDDEN + k];
                acc[i].x = fmaf(a, w.x, acc[i].x);
                acc[i].y = fmaf(a, w.y, acc[i].y);
                acc[i].z = fmaf(a, w.z, acc[i].z);
                acc[i].w = fmaf(a, w.w, acc[i].w);
            }
        }
        __syncthreads();   // all reads of this chunk's source rows done
        #pragma unroll
        for (int i = 0; i < 5; i++) {
            int n = m + 16 * (chunk * 5 + i);
            *(reinterpret_cast<float4*>(sT + n * HIDDEN) + q) = acc[i];
        }
    }
    __syncthreads();

    if (tid < NPB) {
        float mx = -INFINITY;
        #pragma unroll
        for (int k = 0; k < HIDDEN; k++)
            mx = fmaxf(mx, sT[tid * HIDDEN + k]);
        float s = 0.0f;
        #pragma unroll
        for (int k = 0; k < HIDDEN; k++)
            s += expf(sT[tid * HIDDEN + k] - mx);
        sLS[tid] = mx + logf(s);
    }
    __syncthreads();

    #pragma unroll
    for (int i = 0; i < 10; i++) {
        int n = m + 16 * i;
        float ls = sLS[n];
        float4 z = *(reinterpret_cast<const float4*>(sT + n * HIDDEN) + q);
        float4 o;
        o.x = z.x - ls; o.y = z.y - ls; o.z = z.z - ls; o.w = z.w - ls;
        *(reinterpret_cast<float4*>(out + (size_t)base + n * HIDDEN) + q) = o;
    }
}

// ---------------------------------------------------------------------------
extern "C" void kernel_launch(void* const* d_in, const int* in_sizes, int n_in,
                              void* d_out, int out_size) {
    const float* x     = (const float*)d_in[0];
    const int*   ei    = (const int*)  d_in[1];
    const float* W0    = (const float*)d_in[2];
    const float* b0    = (const float*)d_in[3];
    const float* convW = (const float*)d_in[4];
    const float* W1    = (const float*)d_in[5];
    const float* b1    = (const float*)d_in[6];
    float* out = (float*)d_out;

    // beta_l = log(0.5/(l+1) + 1)
    const float betas[4] = {0.4054651081f, 0.2231435513f,
                            0.1541506798f, 0.1177830357f};

    const int it = 256;
    init_kernel<<<(N_NODES * HIDDEN + it - 1) / it, it>>>(x, W0, b0);

    const int et = 256;
    const int eb = (N_EDGES + et - 1) / et;
    hist_kernel<<<eb, et>>>(ei);
    scanA_kernel<<<SCB, 256>>>();
    scanC_kernel<<<SCB, 1024>>>();
    fill_kernel<<<eb, et>>>(ei);

    const int node_blocks = N_NODES / NPB;   // 625
    for (int l = 0; l < 4; l++) {
        gather_kernel<<<node_blocks, LTHREADS>>>(l & 1);
        gemm_kernel<<<node_blocks, LTHREADS>>>(convW + l * HIDDEN * HIDDEN,
                                               betas[l], l & 1);
    }

    // layers 0..3: h path g_h -> g_hb -> g_h -> g_hb -> g_h (final in g_h)
    out_kernel<<<node_blocks, LTHREADS>>>(W1, b1, out);
}